// round 16
// baseline (speedup 1.0000x reference)
#include <cuda_runtime.h>
#include <cuda_bf16.h>
#include <cuda_fp16.h>

// ---------------- static scratch (no runtime allocation allowed) ----------------
#define NMAX 50048
#define EMAX 1664000
#define GMAXG 512

__device__ float   g_feat[(size_t)NMAX * 245];
__device__ float   g_h0[(size_t)NMAX * 128];
__device__ float   g_h2[(size_t)NMAX * 128];
__device__ __half2 g_h0h[(size_t)NMAX * 64];   // fp16 mirror of h0 (gather source)
__device__ __half2 g_h1h[(size_t)NMAX * 64];   // fp16 h1 (gather source)
__device__ float   g_deg[NMAX];
__device__ float   g_dinv[NMAX];
__device__ int     g_indeg[NMAX];
__device__ int     g_off[NMAX + 1];
__device__ int     g_cur[NMAX];
__device__ int2    g_edge[EMAX];
__device__ float   g_bnsum[128];
__device__ float   g_bnsq[128];
__device__ float   g_ab[256];
__device__ float   g_gsum[GMAXG * 128];
__device__ float   g_gcnt[GMAXG];

// ---------------- zero init ----------------
__global__ void k_zero(int n) {
    int i = blockIdx.x * blockDim.x + threadIdx.x;
    if (i < n) { g_deg[i] = 0.f; g_indeg[i] = 0; }
    if (i < 128) { g_bnsum[i] = 0.f; g_bnsq[i] = 0.f; }
    if (i < GMAXG * 128) g_gsum[i] = 0.f;
    if (i < GMAXG) g_gcnt[i] = 0.f;
}

// ---------------- CNN encoder (frozen core) with node-range parameters ---------
#define CNN_NPB 7
#define SM_W1   0
#define SM_W2   224
#define SM_XS   1232
#define SM_C1S  (1232 + CNN_NPB * 1083)
#define CNN_SMEM_FLOATS (SM_C1S + CNN_NPB * 2312)

__global__ __launch_bounds__(256, 2) void k_cnn(
    const float* __restrict__ x,
    const float* __restrict__ c1w, const float* __restrict__ c1b,
    const float* __restrict__ c2w, const float* __restrict__ c2b,
    int nodeBase, int nodeEnd)
{
    extern __shared__ float sm[];
    float* w1  = sm + SM_W1;
    float* w2  = sm + SM_W2;
    float* xs  = sm + SM_XS;
    float* c1s = sm + SM_C1S;

    int t = threadIdx.x;
    int node0 = nodeBase + blockIdx.x * CNN_NPB;
    int nLocal = nodeEnd - node0; if (nLocal > CNN_NPB) nLocal = CNN_NPB;
    if (nLocal <= 0) return;

    for (int i = t; i < 216; i += 256) w1[i] = c1w[i];
    if (t < 8) w1[216 + t] = c1b[t];
    for (int i = t; i < 1000; i += 256) w2[i] = c2w[i];
    if (t < 5) w2[1000 + t] = c2b[t];

    int totx = nLocal * 1083;
    const float* xp = x + (size_t)node0 * 1083;
    for (int i = t; i < totx; i += 256) xs[i] = xp[i];
    __syncthreads();

    int tasks1 = nLocal * 34;
    for (int tt = t; tt < tasks1; tt += 256) {
        int nd  = tt / 34;
        int rid = tt - nd * 34;
        int ocg = rid / 17;
        int oy  = rid - ocg * 17;
        int ocb = ocg * 4;
        const float* xb = xs + nd * 1083;

        float acc[4][17];
#pragma unroll
        for (int o = 0; o < 4; o++) {
            float bias = w1[216 + ocb + o];
#pragma unroll
            for (int ox = 0; ox < 17; ox++) acc[o][ox] = bias;
        }
#pragma unroll
        for (int ic = 0; ic < 3; ic++) {
#pragma unroll
            for (int ky = 0; ky < 3; ky++) {
                const float* rowp = xb + ic * 361 + (oy + ky) * 19;
                float rr[19];
#pragma unroll
                for (int j = 0; j < 19; j++) rr[j] = rowp[j];
#pragma unroll
                for (int o = 0; o < 4; o++) {
                    const float* wp = w1 + (ocb + o) * 27 + ic * 9 + ky * 3;
                    float wa = wp[0], wbv = wp[1], wc = wp[2];
#pragma unroll
                    for (int ox = 0; ox < 17; ox++)
                        acc[o][ox] += rr[ox] * wa + rr[ox + 1] * wbv + rr[ox + 2] * wc;
                }
            }
        }
#pragma unroll
        for (int o = 0; o < 4; o++) {
            float* op = c1s + nd * 2312 + (ocb + o) * 289 + oy * 17;
#pragma unroll
            for (int ox = 0; ox < 17; ox++) op[ox] = fmaxf(acc[o][ox], 0.f);
        }
    }
    __syncthreads();

    {
        int icg = t & 3;
        int pid = t >> 2;
        int nd  = pid / 7;
        int oy  = pid - nd * 7;
        bool valid = (nd < nLocal);
        int ndc = valid ? nd : 0;
        const float* ib = c1s + ndc * 2312;

        float acc[35];
#pragma unroll
        for (int j = 0; j < 35; j++) acc[j] = 0.f;

#pragma unroll
        for (int ii = 0; ii < 2; ii++) {
            int ic = icg * 2 + ii;
#pragma unroll
            for (int ky = 0; ky < 5; ky++) {
                const float* rowp = ib + ic * 289 + (oy * 2 + ky) * 17;
                float rr[17];
#pragma unroll
                for (int j = 0; j < 17; j++) rr[j] = rowp[j];
#pragma unroll
                for (int oc = 0; oc < 5; oc++) {
                    const float* wp = w2 + oc * 200 + ic * 25 + ky * 5;
                    float wv[5];
#pragma unroll
                    for (int kx = 0; kx < 5; kx++) wv[kx] = wp[kx];
#pragma unroll
                    for (int ox = 0; ox < 7; ox++) {
#pragma unroll
                        for (int kx = 0; kx < 5; kx++)
                            acc[oc * 7 + ox] += rr[ox * 2 + kx] * wv[kx];
                    }
                }
            }
        }
#pragma unroll
        for (int j = 0; j < 35; j++) {
            acc[j] += __shfl_xor_sync(0xffffffff, acc[j], 1);
            acc[j] += __shfl_xor_sync(0xffffffff, acc[j], 2);
        }
        if (valid && icg == 0) {
            float* fp = g_feat + (size_t)(node0 + nd) * 245 + oy * 7;
#pragma unroll
            for (int oc = 0; oc < 5; oc++) {
                float bias = w2[1000 + oc];
#pragma unroll
                for (int ox = 0; ox < 7; ox++)
                    fp[oc * 49 + ox] = fmaxf(acc[oc * 7 + ox] + bias, 0.f);
            }
        }
    }
}

// ---------------- degree ----------------
__global__ void k_deg(const int* __restrict__ ei, const float* __restrict__ ea, int E) {
    int e = blockIdx.x * blockDim.x + threadIdx.x;
    if (e >= E) return;
    int c = ei[E + e];
    atomicAdd(&g_deg[c], ea[e]);
    atomicAdd(&g_indeg[c], 1);
}

// ---------------- warp-shuffle scan (+ dinv) ----------------
__global__ __launch_bounds__(1024) void k_scan(int n) {
    __shared__ int ws[32];
    __shared__ int s_carry;
    int t = threadIdx.x;
    int lane = t & 31, wid = t >> 5;
    if (t == 0) s_carry = 0;
    __syncthreads();
    for (int base = 0; base < n; base += 1024) {
        int i = base + t;
        int v = (i < n) ? g_indeg[i] : 0;
        if (i < n) {
            float d = g_deg[i];
            g_dinv[i] = (d > 0.f) ? rsqrtf(d) : 0.f;
        }
        int inc = v;
#pragma unroll
        for (int d = 1; d < 32; d <<= 1) {
            int u = __shfl_up_sync(0xffffffffu, inc, d);
            if (lane >= d) inc += u;
        }
        if (lane == 31) ws[wid] = inc;
        __syncthreads();
        if (wid == 0) {
            int s = ws[lane];
#pragma unroll
            for (int d = 1; d < 32; d <<= 1) {
                int u = __shfl_up_sync(0xffffffffu, s, d);
                if (lane >= d) s += u;
            }
            ws[lane] = s;
        }
        __syncthreads();
        int chunkoff = wid ? ws[wid - 1] : 0;
        int carry = s_carry;
        int excl = carry + chunkoff + inc - v;
        if (i < n) { g_off[i] = excl; g_cur[i] = excl; }
        __syncthreads();
        if (t == 0) s_carry = carry + ws[31];
        __syncthreads();
    }
    if (t == 0) g_off[n] = s_carry;
}

// ---------------- CSR build ----------------
__global__ void k_csr(const int* __restrict__ ei, const float* __restrict__ ea, int E) {
    int e = blockIdx.x * blockDim.x + threadIdx.x;
    if (e >= E) return;
    int r = ei[e];
    int c = ei[E + e];
    float nrm = 0.2f * g_dinv[r] * ea[e] * g_dinv[c];
    int pos = atomicAdd(&g_cur[c], 1);
    g_edge[pos] = make_int2(r, __float_as_int(nrm));
}

// ---------------- l1 GEMM -> h0 (FFMA 128x128 tile) with row-range --------------
__global__ __launch_bounds__(256) void k_l1(const float* __restrict__ l1w,
                                            const float* __restrict__ l1b,
                                            int rowBase0, int n)
{
    __shared__ float As[16 * 132];
    __shared__ float Bs[16 * 132];
    int t = threadIdx.x;
    int tx = t & 15, ty = t >> 4;
    float acc[8][8];
#pragma unroll
    for (int i = 0; i < 8; i++)
#pragma unroll
        for (int j = 0; j < 8; j++) acc[i][j] = 0.f;

    int rowBase = rowBase0 + blockIdx.x * 128;
    for (int k0 = 0; k0 < 245; k0 += 16) {
#pragma unroll
        for (int i = 0; i < 8; i++) {
            int e = t + i * 256;
            int m = e >> 4, kk = e & 15;
            int node = rowBase + m, k = k0 + kk;
            As[kk * 132 + m] = (node < n && k < 245) ? g_feat[(size_t)node * 245 + k] : 0.f;
            Bs[kk * 132 + m] = (k < 245) ? l1w[m * 245 + k] : 0.f;
        }
        __syncthreads();
#pragma unroll
        for (int kk = 0; kk < 16; kk++) {
            const float4* ap = (const float4*)(As + kk * 132 + ty * 8);
            const float4* bp = (const float4*)(Bs + kk * 132 + tx * 8);
            float4 a0 = ap[0], a1 = ap[1];
            float4 b0 = bp[0], b1 = bp[1];
            float a[8] = {a0.x, a0.y, a0.z, a0.w, a1.x, a1.y, a1.z, a1.w};
            float b[8] = {b0.x, b0.y, b0.z, b0.w, b1.x, b1.y, b1.z, b1.w};
#pragma unroll
            for (int i = 0; i < 8; i++)
#pragma unroll
                for (int j = 0; j < 8; j++) acc[i][j] += a[i] * b[j];
        }
        __syncthreads();
    }
    float4 lb0 = ((const float4*)l1b)[tx * 2];
    float4 lb1 = ((const float4*)l1b)[tx * 2 + 1];
    float lb[8] = {lb0.x, lb0.y, lb0.z, lb0.w, lb1.x, lb1.y, lb1.z, lb1.w};
#pragma unroll
    for (int i = 0; i < 8; i++) {
        int node = rowBase + ty * 8 + i;
        if (node >= n) continue;
        float o[8];
#pragma unroll
        for (int j = 0; j < 8; j++) o[j] = fmaxf(acc[i][j] + lb[j], 0.f);
        float4* op = (float4*)(g_h0 + (size_t)node * 128 + tx * 8);
        op[0] = make_float4(o[0], o[1], o[2], o[3]);
        op[1] = make_float4(o[4], o[5], o[6], o[7]);
        __half2* hp = g_h0h + (size_t)node * 64 + tx * 4;
        hp[0] = __floats2half2_rn(o[0], o[1]);
        hp[1] = __floats2half2_rn(o[2], o[3]);
        hp[2] = __floats2half2_rn(o[4], o[5]);
        hp[3] = __floats2half2_rn(o[6], o[7]);
    }
}

// ---------------- APPNP hop: fp16 gather, 4-edge unroll; hop2 fuses BN ---------
__global__ __launch_bounds__(256) void k_hop(int which, int n) {
    __shared__ float ssum[128], ssq[128];
    int t = threadIdx.x;
    if (which) {
        if (t < 128) { ssum[t] = 0.f; ssq[t] = 0.f; }
        __syncthreads();
    }
    int wid = (blockIdx.x * 256 + t) >> 5;
    int lane = t & 31;
    bool valid = (wid < n);

    float4 o = make_float4(0.f, 0.f, 0.f, 0.f);
    if (valid) {
        const __half2* hin = which ? g_h1h : g_h0h;
        int off0 = g_off[wid], off1 = g_off[wid + 1];

        float a0 = 0.f, a1 = 0.f, a2 = 0.f, a3 = 0.f;
        int e = off0;
        for (; e + 4 <= off1; e += 4) {
            int2 r0 = g_edge[e];
            int2 r1 = g_edge[e + 1];
            int2 r2 = g_edge[e + 2];
            int2 r3 = g_edge[e + 3];
            uint2 u0 = *(const uint2*)(hin + (size_t)r0.x * 64 + lane * 2);
            uint2 u1 = *(const uint2*)(hin + (size_t)r1.x * 64 + lane * 2);
            uint2 u2 = *(const uint2*)(hin + (size_t)r2.x * 64 + lane * 2);
            uint2 u3 = *(const uint2*)(hin + (size_t)r3.x * 64 + lane * 2);
            float w0 = __int_as_float(r0.y), w1 = __int_as_float(r1.y);
            float w2 = __int_as_float(r2.y), w3 = __int_as_float(r3.y);
            float2 f;
            f = __half22float2(*(const __half2*)&u0.x); a0 += w0 * f.x; a1 += w0 * f.y;
            f = __half22float2(*(const __half2*)&u0.y); a2 += w0 * f.x; a3 += w0 * f.y;
            f = __half22float2(*(const __half2*)&u1.x); a0 += w1 * f.x; a1 += w1 * f.y;
            f = __half22float2(*(const __half2*)&u1.y); a2 += w1 * f.x; a3 += w1 * f.y;
            f = __half22float2(*(const __half2*)&u2.x); a0 += w2 * f.x; a1 += w2 * f.y;
            f = __half22float2(*(const __half2*)&u2.y); a2 += w2 * f.x; a3 += w2 * f.y;
            f = __half22float2(*(const __half2*)&u3.x); a0 += w3 * f.x; a1 += w3 * f.y;
            f = __half22float2(*(const __half2*)&u3.y); a2 += w3 * f.x; a3 += w3 * f.y;
        }
        for (; e < off1; e++) {
            int2 ra = g_edge[e];
            uint2 ua = *(const uint2*)(hin + (size_t)ra.x * 64 + lane * 2);
            float w0 = __int_as_float(ra.y);
            float2 f;
            f = __half22float2(*(const __half2*)&ua.x); a0 += w0 * f.x; a1 += w0 * f.y;
            f = __half22float2(*(const __half2*)&ua.y); a2 += w0 * f.x; a3 += w0 * f.y;
        }
        float4 h0v = ((const float4*)g_h0)[(size_t)wid * 32 + lane];
        o.x = a0 + 0.8f * h0v.x;
        o.y = a1 + 0.8f * h0v.y;
        o.z = a2 + 0.8f * h0v.z;
        o.w = a3 + 0.8f * h0v.w;
        if (which) {
            ((float4*)g_h2)[(size_t)wid * 32 + lane] = o;
        } else {
            __half2* hp = g_h1h + (size_t)wid * 64 + lane * 2;
            hp[0] = __floats2half2_rn(o.x, o.y);
            hp[1] = __floats2half2_rn(o.z, o.w);
        }
    }
    if (which) {
        if (valid) {
            int c = lane * 4;
            atomicAdd(&ssum[c + 0], o.x); atomicAdd(&ssq[c + 0], o.x * o.x);
            atomicAdd(&ssum[c + 1], o.y); atomicAdd(&ssq[c + 1], o.y * o.y);
            atomicAdd(&ssum[c + 2], o.z); atomicAdd(&ssq[c + 2], o.z * o.z);
            atomicAdd(&ssum[c + 3], o.w); atomicAdd(&ssq[c + 3], o.w * o.w);
        }
        __syncthreads();
        if (t < 128) {
            atomicAdd(&g_bnsum[t], ssum[t]);
            atomicAdd(&g_bnsq[t], ssq[t]);
        }
    }
}

__global__ void k_bnfin(const float* __restrict__ gamma, const float* __restrict__ beta,
                        float invN) {
    int c = threadIdx.x;
    float mean = g_bnsum[c] * invN;
    float var = g_bnsq[c] * invN - mean * mean;
    float inv = rsqrtf(var + 1e-5f);
    float a = gamma[c] * inv;
    g_ab[c] = a;
    g_ab[128 + c] = beta[c] - mean * a;
}

// ---------------- normalize + write node_x + pool (block-aggregated atomics) ---
__global__ __launch_bounds__(256) void k_pool(const int* __restrict__ batch,
                                              float* __restrict__ out, int n) {
    __shared__ float ssum[128];
    __shared__ int sg[8];
    int t = threadIdx.x;
    int w = t >> 5, lane = t & 31;
    int node = blockIdx.x * 8 + w;
    bool valid = (node < n);
    if (lane == 0) sg[w] = valid ? batch[node] : -1;
    if (t < 128) ssum[t] = 0.f;
    __syncthreads();
    int g0 = sg[0];
    bool uniform = true;
#pragma unroll
    for (int i = 1; i < 8; i++) uniform &= (sg[i] == g0 || sg[i] < 0);

    int c = lane * 4;
    float4 r = make_float4(0.f, 0.f, 0.f, 0.f);
    if (valid) {
        float4 v = ((const float4*)g_h2)[(size_t)node * 32 + lane];
        r.x = v.x * g_ab[c + 0] + g_ab[128 + c + 0];
        r.y = v.y * g_ab[c + 1] + g_ab[128 + c + 1];
        r.z = v.z * g_ab[c + 2] + g_ab[128 + c + 2];
        r.w = v.w * g_ab[c + 3] + g_ab[128 + c + 3];
        ((float4*)out)[640 + (size_t)node * 32 + lane] = r;
        if (uniform) {
            atomicAdd(&ssum[c + 0], r.x);
            atomicAdd(&ssum[c + 1], r.y);
            atomicAdd(&ssum[c + 2], r.z);
            atomicAdd(&ssum[c + 3], r.w);
        } else {
            int g = sg[w];
            float* gp = g_gsum + (size_t)g * 128 + c;
            atomicAdd(gp + 0, r.x);
            atomicAdd(gp + 1, r.y);
            atomicAdd(gp + 2, r.z);
            atomicAdd(gp + 3, r.w);
        }
    }
    __syncthreads();
    if (uniform && t < 128)
        atomicAdd(&g_gsum[(size_t)g0 * 128 + t], ssum[t]);
}

__global__ void k_gcnt(const int* __restrict__ batch, int n) {
    int i = blockIdx.x * blockDim.x + threadIdx.x;
    if (i >= n) return;
    atomicAdd(&g_gcnt[batch[i]], 1.0f);
}

// ---------------- graph MLP classifier ----------------
__global__ __launch_bounds__(64) void k_mlp(const float* __restrict__ l2w,
                                            const float* __restrict__ l2b,
                                            const float* __restrict__ l3w,
                                            const float* __restrict__ l3b,
                                            float* __restrict__ out) {
    int g = blockIdx.x, t = threadIdx.x;
    __shared__ float gx[128], hid[64];
    float cnt = fmaxf(g_gcnt[g], 1.f);
    float ic = 1.f / cnt;
    gx[t]      = g_gsum[(size_t)g * 128 + t] * ic;
    gx[t + 64] = g_gsum[(size_t)g * 128 + 64 + t] * ic;
    __syncthreads();
    float s = l2b[t];
    const float* wr = l2w + t * 128;
#pragma unroll 8
    for (int c = 0; c < 128; c++) s += gx[c] * wr[c];
    hid[t] = fmaxf(s, 0.f);
    __syncthreads();
    if (t < 5) {
        float s2 = l3b[t];
        const float* wr3 = l3w + t * 64;
#pragma unroll 8
        for (int j = 0; j < 64; j++) s2 += hid[j] * wr3[j];
        out[g * 5 + t] = s2;
    }
}

// ---------------- launcher: pipelined cnn/l1 chunks + edge-chain overlap -------
extern "C" void kernel_launch(void* const* d_in, const int* in_sizes, int n_in,
                              void* d_out, int out_size) {
    static cudaStream_t sB = nullptr, sC = nullptr;
    static cudaEvent_t evFork = nullptr, evJoin = nullptr, evC0 = nullptr, evL0 = nullptr;
    if (sB == nullptr) {
        cudaStreamCreateWithFlags(&sB, cudaStreamNonBlocking);
        cudaStreamCreateWithFlags(&sC, cudaStreamNonBlocking);
        cudaEventCreateWithFlags(&evFork, cudaEventDisableTiming);
        cudaEventCreateWithFlags(&evJoin, cudaEventDisableTiming);
        cudaEventCreateWithFlags(&evC0, cudaEventDisableTiming);
        cudaEventCreateWithFlags(&evL0, cudaEventDisableTiming);
    }

    int wb = (n_in > 4 && in_sizes[4] == 216) ? 4 : 5;

    const float* x     = (const float*)d_in[0];
    const int*   ei    = (const int*)d_in[1];
    const float* ea    = (const float*)d_in[2];
    const int*   batch = (const int*)d_in[3];
    const float* c1w = (const float*)d_in[wb + 0];
    const float* c1b = (const float*)d_in[wb + 1];
    const float* c2w = (const float*)d_in[wb + 2];
    const float* c2b = (const float*)d_in[wb + 3];
    const float* l1w = (const float*)d_in[wb + 4];
    const float* l1b = (const float*)d_in[wb + 5];
    const float* gam = (const float*)d_in[wb + 6];
    const float* bet = (const float*)d_in[wb + 7];
    const float* l2w = (const float*)d_in[wb + 8];
    const float* l2b = (const float*)d_in[wb + 9];
    const float* l3w = (const float*)d_in[wb + 10];
    const float* l3b = (const float*)d_in[wb + 11];

    int n = in_sizes[0] / 1083;
    int E = in_sizes[1] / 2;
    int G = (out_size - n * 128) / 5;
    float* out = (float*)d_out;

    int cnnSmem = CNN_SMEM_FLOATS * 4;
    cudaFuncSetAttribute(k_cnn, cudaFuncAttributeMaxDynamicSharedMemorySize, cnnSmem);

    // chunk boundary: multiple of lcm(7,128)=896, ~half of n
    int half = ((n / 2) / 896) * 896;
    if (half <= 0 || half >= n) half = n;  // degenerate: single chunk
    int c0 = half, c1n = n - half;

    // stream 0: zero, then fork (proven ordering)
    k_zero<<<(GMAXG * 128 + 255) / 256, 256>>>(n);
    cudaEventRecord(evFork, 0);
    cudaStreamWaitEvent(sB, evFork, 0);

    // stream B: edge preprocessing chain (hidden under node path)
    k_deg<<<(E + 255) / 256, 256, 0, sB>>>(ei, ea, E);
    k_scan<<<1, 1024, 0, sB>>>(n);
    k_csr<<<(E + 255) / 256, 256, 0, sB>>>(ei, ea, E);
    k_gcnt<<<(n + 255) / 256, 256, 0, sB>>>(batch, n);
    cudaEventRecord(evJoin, sB);

    // stream 0: cnn chunk0, then cnn chunk1; l1 chunk0 pipelined on stream C
    k_cnn<<<(c0 + CNN_NPB - 1) / CNN_NPB, 256, cnnSmem>>>(x, c1w, c1b, c2w, c2b, 0, c0);
    cudaEventRecord(evC0, 0);
    if (c1n > 0)
        k_cnn<<<(c1n + CNN_NPB - 1) / CNN_NPB, 256, cnnSmem>>>(x, c1w, c1b, c2w, c2b, c0, n);

    cudaStreamWaitEvent(sC, evC0, 0);
    k_l1<<<(c0 + 127) / 128, 256, 0, sC>>>(l1w, l1b, 0, n);
    cudaEventRecord(evL0, sC);

    if (c1n > 0)
        k_l1<<<(c1n + 127) / 128, 256>>>(l1w, l1b, c0, n);

    // join all producers, then the dependent tail
    cudaStreamWaitEvent(0, evL0, 0);
    cudaStreamWaitEvent(0, evJoin, 0);
    int hopBlocks = (n * 32 + 255) / 256;
    k_hop<<<hopBlocks, 256>>>(0, n);
    k_hop<<<hopBlocks, 256>>>(1, n);   // fused BN stats

    k_bnfin<<<1, 128>>>(gam, bet, 1.0f / (float)n);
    k_pool<<<(n + 7) / 8, 256>>>(batch, out, n);
    k_mlp<<<G, 64>>>(l2w, l2b, l3w, l3b, out);
}

// round 17
// speedup vs baseline: 1.0192x; 1.0192x over previous
#include <cuda_runtime.h>
#include <cuda_bf16.h>
#include <cuda_fp16.h>

// ---------------- static scratch (no runtime allocation allowed) ----------------
#define NMAX 50048
#define EMAX 1664000
#define GMAXG 512

__device__ float   g_feat[(size_t)NMAX * 245];
__device__ float   g_h0[(size_t)NMAX * 128];
__device__ float   g_h2[(size_t)NMAX * 128];
__device__ __half2 g_h0h[(size_t)NMAX * 64];   // fp16 mirror of h0 (gather source)
__device__ __half2 g_h1h[(size_t)NMAX * 64];   // fp16 h1 (gather source)
__device__ float   g_deg[NMAX];
__device__ float   g_dinv[NMAX];
__device__ int     g_indeg[NMAX];
__device__ int     g_off[NMAX + 1];
__device__ int     g_cur[NMAX];
__device__ int2    g_edge[EMAX];
__device__ float   g_bnsum[128];
__device__ float   g_bnsq[128];
__device__ float   g_gsum[GMAXG * 128];
__device__ float   g_gcnt[GMAXG];

// ---------------- zero init ----------------
__global__ void k_zero(int n) {
    int i = blockIdx.x * blockDim.x + threadIdx.x;
    if (i < n) { g_deg[i] = 0.f; g_indeg[i] = 0; }
    if (i < 128) { g_bnsum[i] = 0.f; g_bnsq[i] = 0.f; }
    if (i < GMAXG * 128) g_gsum[i] = 0.f;
    if (i < GMAXG) g_gcnt[i] = 0.f;
}

// ---------------- CNN encoder (R11 frozen): oc-grouped register tiles ----------
#define CNN_NPB 7
#define SM_W1   0
#define SM_W2   224
#define SM_XS   1232
#define SM_C1S  (1232 + CNN_NPB * 1083)
#define CNN_SMEM_FLOATS (SM_C1S + CNN_NPB * 2312)

__global__ __launch_bounds__(256, 2) void k_cnn(
    const float* __restrict__ x,
    const float* __restrict__ c1w, const float* __restrict__ c1b,
    const float* __restrict__ c2w, const float* __restrict__ c2b, int n)
{
    extern __shared__ float sm[];
    float* w1  = sm + SM_W1;
    float* w2  = sm + SM_W2;
    float* xs  = sm + SM_XS;
    float* c1s = sm + SM_C1S;

    int t = threadIdx.x;
    int node0 = blockIdx.x * CNN_NPB;
    int nLocal = n - node0; if (nLocal > CNN_NPB) nLocal = CNN_NPB;
    if (nLocal <= 0) return;

    for (int i = t; i < 216; i += 256) w1[i] = c1w[i];
    if (t < 8) w1[216 + t] = c1b[t];
    for (int i = t; i < 1000; i += 256) w2[i] = c2w[i];
    if (t < 5) w2[1000 + t] = c2b[t];

    int totx = nLocal * 1083;
    const float* xp = x + (size_t)node0 * 1083;
    for (int i = t; i < totx; i += 256) xs[i] = xp[i];
    __syncthreads();

    int tasks1 = nLocal * 34;
    for (int tt = t; tt < tasks1; tt += 256) {
        int nd  = tt / 34;
        int rid = tt - nd * 34;
        int ocg = rid / 17;
        int oy  = rid - ocg * 17;
        int ocb = ocg * 4;
        const float* xb = xs + nd * 1083;

        float acc[4][17];
#pragma unroll
        for (int o = 0; o < 4; o++) {
            float bias = w1[216 + ocb + o];
#pragma unroll
            for (int ox = 0; ox < 17; ox++) acc[o][ox] = bias;
        }
#pragma unroll
        for (int ic = 0; ic < 3; ic++) {
#pragma unroll
            for (int ky = 0; ky < 3; ky++) {
                const float* rowp = xb + ic * 361 + (oy + ky) * 19;
                float rr[19];
#pragma unroll
                for (int j = 0; j < 19; j++) rr[j] = rowp[j];
#pragma unroll
                for (int o = 0; o < 4; o++) {
                    const float* wp = w1 + (ocb + o) * 27 + ic * 9 + ky * 3;
                    float wa = wp[0], wbv = wp[1], wc = wp[2];
#pragma unroll
                    for (int ox = 0; ox < 17; ox++)
                        acc[o][ox] += rr[ox] * wa + rr[ox + 1] * wbv + rr[ox + 2] * wc;
                }
            }
        }
#pragma unroll
        for (int o = 0; o < 4; o++) {
            float* op = c1s + nd * 2312 + (ocb + o) * 289 + oy * 17;
#pragma unroll
            for (int ox = 0; ox < 17; ox++) op[ox] = fmaxf(acc[o][ox], 0.f);
        }
    }
    __syncthreads();

    {
        int icg = t & 3;
        int pid = t >> 2;
        int nd  = pid / 7;
        int oy  = pid - nd * 7;
        bool valid = (nd < nLocal);
        int ndc = valid ? nd : 0;
        const float* ib = c1s + ndc * 2312;

        float acc[35];
#pragma unroll
        for (int j = 0; j < 35; j++) acc[j] = 0.f;

#pragma unroll
        for (int ii = 0; ii < 2; ii++) {
            int ic = icg * 2 + ii;
#pragma unroll
            for (int ky = 0; ky < 5; ky++) {
                const float* rowp = ib + ic * 289 + (oy * 2 + ky) * 17;
                float rr[17];
#pragma unroll
                for (int j = 0; j < 17; j++) rr[j] = rowp[j];
#pragma unroll
                for (int oc = 0; oc < 5; oc++) {
                    const float* wp = w2 + oc * 200 + ic * 25 + ky * 5;
                    float wv[5];
#pragma unroll
                    for (int kx = 0; kx < 5; kx++) wv[kx] = wp[kx];
#pragma unroll
                    for (int ox = 0; ox < 7; ox++) {
#pragma unroll
                        for (int kx = 0; kx < 5; kx++)
                            acc[oc * 7 + ox] += rr[ox * 2 + kx] * wv[kx];
                    }
                }
            }
        }
#pragma unroll
        for (int j = 0; j < 35; j++) {
            acc[j] += __shfl_xor_sync(0xffffffff, acc[j], 1);
            acc[j] += __shfl_xor_sync(0xffffffff, acc[j], 2);
        }
        if (valid && icg == 0) {
            float* fp = g_feat + (size_t)(node0 + nd) * 245 + oy * 7;
#pragma unroll
            for (int oc = 0; oc < 5; oc++) {
                float bias = w2[1000 + oc];
#pragma unroll
                for (int ox = 0; ox < 7; ox++)
                    fp[oc * 49 + ox] = fmaxf(acc[oc * 7 + ox] + bias, 0.f);
            }
        }
    }
}

// ---------------- degree ----------------
__global__ void k_deg(const int* __restrict__ ei, const float* __restrict__ ea, int E) {
    int e = blockIdx.x * blockDim.x + threadIdx.x;
    if (e >= E) return;
    int c = ei[E + e];
    atomicAdd(&g_deg[c], ea[e]);
    atomicAdd(&g_indeg[c], 1);
}

// ---------------- warp-shuffle scan (+ dinv) ----------------
__global__ __launch_bounds__(1024) void k_scan(int n) {
    __shared__ int ws[32];
    __shared__ int s_carry;
    int t = threadIdx.x;
    int lane = t & 31, wid = t >> 5;
    if (t == 0) s_carry = 0;
    __syncthreads();
    for (int base = 0; base < n; base += 1024) {
        int i = base + t;
        int v = (i < n) ? g_indeg[i] : 0;
        if (i < n) {
            float d = g_deg[i];
            g_dinv[i] = (d > 0.f) ? rsqrtf(d) : 0.f;
        }
        int inc = v;
#pragma unroll
        for (int d = 1; d < 32; d <<= 1) {
            int u = __shfl_up_sync(0xffffffffu, inc, d);
            if (lane >= d) inc += u;
        }
        if (lane == 31) ws[wid] = inc;
        __syncthreads();
        if (wid == 0) {
            int s = ws[lane];
#pragma unroll
            for (int d = 1; d < 32; d <<= 1) {
                int u = __shfl_up_sync(0xffffffffu, s, d);
                if (lane >= d) s += u;
            }
            ws[lane] = s;
        }
        __syncthreads();
        int chunkoff = wid ? ws[wid - 1] : 0;
        int carry = s_carry;
        int excl = carry + chunkoff + inc - v;
        if (i < n) { g_off[i] = excl; g_cur[i] = excl; }
        __syncthreads();
        if (t == 0) s_carry = carry + ws[31];
        __syncthreads();
    }
    if (t == 0) g_off[n] = s_carry;
}

// ---------------- CSR build ----------------
__global__ void k_csr(const int* __restrict__ ei, const float* __restrict__ ea, int E) {
    int e = blockIdx.x * blockDim.x + threadIdx.x;
    if (e >= E) return;
    int r = ei[e];
    int c = ei[E + e];
    float nrm = 0.2f * g_dinv[r] * ea[e] * g_dinv[c];
    int pos = atomicAdd(&g_cur[c], 1);
    g_edge[pos] = make_int2(r, __float_as_int(nrm));
}

// ---------------- l1 GEMM -> h0 (R11 proven FFMA 128x128 tile) ----------------
__global__ __launch_bounds__(256) void k_l1(const float* __restrict__ l1w,
                                            const float* __restrict__ l1b, int n)
{
    __shared__ float As[16 * 132];
    __shared__ float Bs[16 * 132];
    int t = threadIdx.x;
    int tx = t & 15, ty = t >> 4;
    float acc[8][8];
#pragma unroll
    for (int i = 0; i < 8; i++)
#pragma unroll
        for (int j = 0; j < 8; j++) acc[i][j] = 0.f;

    int rowBase = blockIdx.x * 128;
    for (int k0 = 0; k0 < 245; k0 += 16) {
#pragma unroll
        for (int i = 0; i < 8; i++) {
            int e = t + i * 256;
            int m = e >> 4, kk = e & 15;
            int node = rowBase + m, k = k0 + kk;
            As[kk * 132 + m] = (node < n && k < 245) ? g_feat[(size_t)node * 245 + k] : 0.f;
            Bs[kk * 132 + m] = (k < 245) ? l1w[m * 245 + k] : 0.f;
        }
        __syncthreads();
#pragma unroll
        for (int kk = 0; kk < 16; kk++) {
            const float4* ap = (const float4*)(As + kk * 132 + ty * 8);
            const float4* bp = (const float4*)(Bs + kk * 132 + tx * 8);
            float4 a0 = ap[0], a1 = ap[1];
            float4 b0 = bp[0], b1 = bp[1];
            float a[8] = {a0.x, a0.y, a0.z, a0.w, a1.x, a1.y, a1.z, a1.w};
            float b[8] = {b0.x, b0.y, b0.z, b0.w, b1.x, b1.y, b1.z, b1.w};
#pragma unroll
            for (int i = 0; i < 8; i++)
#pragma unroll
                for (int j = 0; j < 8; j++) acc[i][j] += a[i] * b[j];
        }
        __syncthreads();
    }
    float4 lb0 = ((const float4*)l1b)[tx * 2];
    float4 lb1 = ((const float4*)l1b)[tx * 2 + 1];
    float lb[8] = {lb0.x, lb0.y, lb0.z, lb0.w, lb1.x, lb1.y, lb1.z, lb1.w};
#pragma unroll
    for (int i = 0; i < 8; i++) {
        int node = rowBase + ty * 8 + i;
        if (node >= n) continue;
        float o[8];
#pragma unroll
        for (int j = 0; j < 8; j++) o[j] = fmaxf(acc[i][j] + lb[j], 0.f);
        float4* op = (float4*)(g_h0 + (size_t)node * 128 + tx * 8);
        op[0] = make_float4(o[0], o[1], o[2], o[3]);
        op[1] = make_float4(o[4], o[5], o[6], o[7]);
        __half2* hp = g_h0h + (size_t)node * 64 + tx * 4;
        hp[0] = __floats2half2_rn(o[0], o[1]);
        hp[1] = __floats2half2_rn(o[2], o[3]);
        hp[2] = __floats2half2_rn(o[4], o[5]);
        hp[3] = __floats2half2_rn(o[6], o[7]);
    }
}

// ---------------- APPNP hop: fp16 gather, 8-edge unroll; hop2 fuses BN ---------
__global__ __launch_bounds__(256) void k_hop(int which, int n) {
    __shared__ float ssum[128], ssq[128];
    int t = threadIdx.x;
    if (which) {
        if (t < 128) { ssum[t] = 0.f; ssq[t] = 0.f; }
        __syncthreads();
    }
    int wid = (blockIdx.x * 256 + t) >> 5;
    int lane = t & 31;
    bool valid = (wid < n);

    float4 o = make_float4(0.f, 0.f, 0.f, 0.f);
    if (valid) {
        const __half2* hin = which ? g_h1h : g_h0h;
        int off0 = g_off[wid], off1 = g_off[wid + 1];

        float a0 = 0.f, a1 = 0.f, a2 = 0.f, a3 = 0.f;
        int e = off0;
        for (; e + 8 <= off1; e += 8) {
            int2 rr[8];
            uint2 uu[8];
#pragma unroll
            for (int q = 0; q < 8; q++) rr[q] = g_edge[e + q];
#pragma unroll
            for (int q = 0; q < 8; q++)
                uu[q] = *(const uint2*)(hin + (size_t)rr[q].x * 64 + lane * 2);
#pragma unroll
            for (int q = 0; q < 8; q++) {
                float w = __int_as_float(rr[q].y);
                float2 f0 = __half22float2(*(const __half2*)&uu[q].x);
                float2 f1 = __half22float2(*(const __half2*)&uu[q].y);
                a0 += w * f0.x; a1 += w * f0.y; a2 += w * f1.x; a3 += w * f1.y;
            }
        }
        for (; e < off1; e++) {
            int2 ra = g_edge[e];
            uint2 ua = *(const uint2*)(hin + (size_t)ra.x * 64 + lane * 2);
            float w0 = __int_as_float(ra.y);
            float2 f;
            f = __half22float2(*(const __half2*)&ua.x); a0 += w0 * f.x; a1 += w0 * f.y;
            f = __half22float2(*(const __half2*)&ua.y); a2 += w0 * f.x; a3 += w0 * f.y;
        }
        float4 h0v = ((const float4*)g_h0)[(size_t)wid * 32 + lane];
        o.x = a0 + 0.8f * h0v.x;
        o.y = a1 + 0.8f * h0v.y;
        o.z = a2 + 0.8f * h0v.z;
        o.w = a3 + 0.8f * h0v.w;
        if (which) {
            ((float4*)g_h2)[(size_t)wid * 32 + lane] = o;
        } else {
            __half2* hp = g_h1h + (size_t)wid * 64 + lane * 2;
            hp[0] = __floats2half2_rn(o.x, o.y);
            hp[1] = __floats2half2_rn(o.z, o.w);
        }
    }
    if (which) {
        if (valid) {
            int c = lane * 4;
            atomicAdd(&ssum[c + 0], o.x); atomicAdd(&ssq[c + 0], o.x * o.x);
            atomicAdd(&ssum[c + 1], o.y); atomicAdd(&ssq[c + 1], o.y * o.y);
            atomicAdd(&ssum[c + 2], o.z); atomicAdd(&ssq[c + 2], o.z * o.z);
            atomicAdd(&ssum[c + 3], o.w); atomicAdd(&ssq[c + 3], o.w * o.w);
        }
        __syncthreads();
        if (t < 128) {
            atomicAdd(&g_bnsum[t], ssum[t]);
            atomicAdd(&g_bnsq[t], ssq[t]);
        }
    }
}

// ---------------- normalize + node_x + pool; BN finalize fused per block -------
__global__ __launch_bounds__(256) void k_pool(const int* __restrict__ batch,
                                              const float* __restrict__ gamma,
                                              const float* __restrict__ beta,
                                              float invN,
                                              float* __restrict__ out, int n) {
    __shared__ float ssum[128];
    __shared__ float sa[128], sb[128];
    __shared__ int sg[8];
    int t = threadIdx.x;
    int w = t >> 5, lane = t & 31;
    int node = blockIdx.x * 8 + w;
    bool valid = (node < n);
    if (lane == 0) sg[w] = valid ? batch[node] : -1;
    if (t < 128) {
        ssum[t] = 0.f;
        float mean = g_bnsum[t] * invN;
        float var = g_bnsq[t] * invN - mean * mean;
        float a = gamma[t] * rsqrtf(var + 1e-5f);
        sa[t] = a;
        sb[t] = beta[t] - mean * a;
    }
    __syncthreads();
    int g0 = sg[0];
    bool uniform = true;
#pragma unroll
    for (int i = 1; i < 8; i++) uniform &= (sg[i] == g0 || sg[i] < 0);

    int c = lane * 4;
    float4 r = make_float4(0.f, 0.f, 0.f, 0.f);
    if (valid) {
        float4 v = ((const float4*)g_h2)[(size_t)node * 32 + lane];
        r.x = v.x * sa[c + 0] + sb[c + 0];
        r.y = v.y * sa[c + 1] + sb[c + 1];
        r.z = v.z * sa[c + 2] + sb[c + 2];
        r.w = v.w * sa[c + 3] + sb[c + 3];
        ((float4*)out)[640 + (size_t)node * 32 + lane] = r;
        if (uniform) {
            atomicAdd(&ssum[c + 0], r.x);
            atomicAdd(&ssum[c + 1], r.y);
            atomicAdd(&ssum[c + 2], r.z);
            atomicAdd(&ssum[c + 3], r.w);
        } else {
            int g = sg[w];
            float* gp = g_gsum + (size_t)g * 128 + c;
            atomicAdd(gp + 0, r.x);
            atomicAdd(gp + 1, r.y);
            atomicAdd(gp + 2, r.z);
            atomicAdd(gp + 3, r.w);
        }
    }
    __syncthreads();
    if (uniform && t < 128)
        atomicAdd(&g_gsum[(size_t)g0 * 128 + t], ssum[t]);
}

__global__ void k_gcnt(const int* __restrict__ batch, int n) {
    int i = blockIdx.x * blockDim.x + threadIdx.x;
    if (i >= n) return;
    atomicAdd(&g_gcnt[batch[i]], 1.0f);
}

// ---------------- graph MLP classifier ----------------
__global__ __launch_bounds__(64) void k_mlp(const float* __restrict__ l2w,
                                            const float* __restrict__ l2b,
                                            const float* __restrict__ l3w,
                                            const float* __restrict__ l3b,
                                            float* __restrict__ out) {
    int g = blockIdx.x, t = threadIdx.x;
    __shared__ float gx[128], hid[64];
    float cnt = fmaxf(g_gcnt[g], 1.f);
    float ic = 1.f / cnt;
    gx[t]      = g_gsum[(size_t)g * 128 + t] * ic;
    gx[t + 64] = g_gsum[(size_t)g * 128 + 64 + t] * ic;
    __syncthreads();
    float s = l2b[t];
    const float* wr = l2w + t * 128;
#pragma unroll 8
    for (int c = 0; c < 128; c++) s += gx[c] * wr[c];
    hid[t] = fmaxf(s, 0.f);
    __syncthreads();
    if (t < 5) {
        float s2 = l3b[t];
        const float* wr3 = l3w + t * 64;
#pragma unroll 8
        for (int j = 0; j < 64; j++) s2 += hid[j] * wr3[j];
        out[g * 5 + t] = s2;
    }
}

// ---------------- launcher (R15 proven topology) ----------------
extern "C" void kernel_launch(void* const* d_in, const int* in_sizes, int n_in,
                              void* d_out, int out_size) {
    static cudaStream_t sB = nullptr;
    static cudaEvent_t evFork = nullptr, evJoin = nullptr;
    if (sB == nullptr) {
        cudaStreamCreateWithFlags(&sB, cudaStreamNonBlocking);
        cudaEventCreateWithFlags(&evFork, cudaEventDisableTiming);
        cudaEventCreateWithFlags(&evJoin, cudaEventDisableTiming);
    }

    int wb = (n_in > 4 && in_sizes[4] == 216) ? 4 : 5;

    const float* x     = (const float*)d_in[0];
    const int*   ei    = (const int*)d_in[1];
    const float* ea    = (const float*)d_in[2];
    const int*   batch = (const int*)d_in[3];
    const float* c1w = (const float*)d_in[wb + 0];
    const float* c1b = (const float*)d_in[wb + 1];
    const float* c2w = (const float*)d_in[wb + 2];
    const float* c2b = (const float*)d_in[wb + 3];
    const float* l1w = (const float*)d_in[wb + 4];
    const float* l1b = (const float*)d_in[wb + 5];
    const float* gam = (const float*)d_in[wb + 6];
    const float* bet = (const float*)d_in[wb + 7];
    const float* l2w = (const float*)d_in[wb + 8];
    const float* l2b = (const float*)d_in[wb + 9];
    const float* l3w = (const float*)d_in[wb + 10];
    const float* l3b = (const float*)d_in[wb + 11];

    int n = in_sizes[0] / 1083;
    int E = in_sizes[1] / 2;
    int G = (out_size - n * 128) / 5;
    float* out = (float*)d_out;

    int cnnSmem = CNN_SMEM_FLOATS * 4;
    cudaFuncSetAttribute(k_cnn, cudaFuncAttributeMaxDynamicSharedMemorySize, cnnSmem);

    // stream 0: zero, then fork (proven ordering)
    k_zero<<<(GMAXG * 128 + 255) / 256, 256>>>(n);
    cudaEventRecord(evFork, 0);
    cudaStreamWaitEvent(sB, evFork, 0);

    // stream B: edge preprocessing chain (hidden under node path)
    k_deg<<<(E + 255) / 256, 256, 0, sB>>>(ei, ea, E);
    k_scan<<<1, 1024, 0, sB>>>(n);
    k_csr<<<(E + 255) / 256, 256, 0, sB>>>(ei, ea, E);
    k_gcnt<<<(n + 255) / 256, 256, 0, sB>>>(batch, n);
    cudaEventRecord(evJoin, sB);

    // stream 0: node encoder path (overlaps with stream B)
    k_cnn<<<(n + CNN_NPB - 1) / CNN_NPB, 256, cnnSmem>>>(x, c1w, c1b, c2w, c2b, n);
    k_l1<<<(n + 127) / 128, 256>>>(l1w, l1b, n);

    // join, then the dependent tail
    cudaStreamWaitEvent(0, evJoin, 0);
    int hopBlocks = (n * 32 + 255) / 256;
    k_hop<<<hopBlocks, 256>>>(0, n);
    k_hop<<<hopBlocks, 256>>>(1, n);   // fused BN stats

    k_pool<<<(n + 7) / 8, 256>>>(batch, gam, bet, 1.0f / (float)n, out, n);
    k_mlp<<<G, 64>>>(l2w, l2b, l3w, l3b, out);
}